// round 1
// baseline (speedup 1.0000x reference)
#include <cuda_runtime.h>
#include <cuda_bf16.h>

// GivensRotationPerHead: H=64 heads, DIM=128, R=8128 rotations (triu order).
// Fast-Givens (2 FFMA/rotation) + 4-row register blocking + SMEM-resident Q.
// One CTA per head, thread t owns column t.

#define NHEADS 64
#define DIMN   128
#define NROT   8128
#define TPB    128

// r index of rotation (i,j): rbase(i) + (j-i-1)
__device__ __forceinline__ int rbase(int i) { return i * 127 - (i * (i - 1)) / 2; }
// start position of block b in the blocked AB table
__device__ __forceinline__ int blockbase(int b) { return 502 * b - 8 * b * (b - 1); }

// fast-givens update: vi' = vi + a*vj ; vj' = b*vi_old + vj
__device__ __forceinline__ void frot(float& vi, float& vj, float a, float b) {
    float ni = fmaf(a, vj, vi);
    vj = fmaf(b, vi, vj);
    vi = ni;
}

// dynamic smem layout (floats):
//   [0, 32512)        C   (cos per rotation)        } region1: after the
//   [32512, 65024)    T   (tan per rotation)        } alpha/beta pass these
//   [65024, 97536)    Fi  (prefix scale, i-role)    } 4 arrays are dead and
//   [97536, 130048)   Fj  (prefix scale, j-role)    } Q[128][128] aliases [0,16384)
//   [32512*4 .. +16256*fl2) AB (alpha,beta) pairs, blocked order (float2 x 8128)
//   [48768, 48896)    rowscale[128]
#define SM_FLOATS (4 * NROT + 2 * NROT + DIMN)   // 48896 floats = 195584 bytes

__global__ __launch_bounds__(TPB)
void givens_kernel(const float* __restrict__ thetas,
                   const int*   __restrict__ rot_i,
                   const int*   __restrict__ rot_j,
                   float*       __restrict__ out)
{
    extern __shared__ float sm[];
    float*  C        = sm;
    float*  T        = sm + NROT;
    float*  Fi       = sm + 2 * NROT;
    float*  Fj       = sm + 3 * NROT;
    float*  Qs       = sm;                       // aliases C/T/Fi (used later)
    float2* AB       = (float2*)(sm + 4 * NROT);
    float*  rowscale = sm + 4 * NROT + 2 * NROT;

    const int tid = threadIdx.x;
    const int h   = blockIdx.x;
    const float* th = thetas + (size_t)h * NROT;

    // ---- pass 1: c = cos(theta), t = tan(theta) ----
    for (int r = tid; r < NROT; r += TPB) {
        float s, c;
        __sincosf(th[r], &s, &c);
        C[r] = c;
        T[r] = __fdividef(s, c);
    }
    __syncthreads();

    // ---- pass 2: per-row prefix products of c (row m = tid) ----
    {
        const int m = tid;
        float f = 1.0f;
        // j-role: rotations (k, m), k < m, in global order
        for (int k = 0; k < m; ++k) {
            int r = rbase(k) + (m - k - 1);
            Fj[r] = f;
            f *= C[r];
        }
        // i-role: rotations (m, j), j > m (contiguous r range)
        int b0 = rbase(m);
        for (int j = m + 1; j < DIMN; ++j) {
            int r = b0 + (j - m - 1);
            Fi[r] = f;
            f *= C[r];
        }
        rowscale[m] = f;
    }
    __syncthreads();

    // ---- pass 3: alpha/beta into blocked AB table ----
    for (int r = tid; r < NROT; r += TPB) {
        int i = rot_i[r];
        int j = rot_j[r];
        float t  = T[r];
        float fi = Fi[r];
        float fj = Fj[r];
        float al =  t * __fdividef(fj, fi);
        float be = -t * __fdividef(fi, fj);
        int b  = i >> 2;
        int a  = i & 3;
        int i0 = b << 2;
        int bb = blockbase(b);
        int pos;
        if (j < i0 + 4) {                     // intra-block triangle (6 slots)
            int jj = j - i0;
            pos = bb + a * 3 - (a * (a - 1)) / 2 + (jj - a - 1);
        } else {
            pos = bb + 6 + ((j - i0 - 4) << 2) + a;
        }
        AB[pos] = make_float2(al, be);
    }
    __syncthreads();

    // ---- init Q~ = I (thread t writes only column t) ----
    for (int idx = tid; idx < DIMN * DIMN; idx += TPB)
        Qs[idx] = ((idx >> 7) == (idx & 127)) ? 1.0f : 0.0f;
    __syncthreads();

    // ---- main loop: 32 blocks of 4 rows held in registers ----
    {
        const int t = tid;
        for (int b = 0; b < 32; ++b) {
            const int i0 = b << 2;
            float v0 = Qs[(i0 + 0) * DIMN + t];
            float v1 = Qs[(i0 + 1) * DIMN + t];
            float v2 = Qs[(i0 + 2) * DIMN + t];
            float v3 = Qs[(i0 + 3) * DIMN + t];
            const int bb = blockbase(b);

            // intra-block triangle in original order
            float2 ab;
            ab = AB[bb + 0]; frot(v0, v1, ab.x, ab.y);
            ab = AB[bb + 1]; frot(v0, v2, ab.x, ab.y);
            ab = AB[bb + 2]; frot(v0, v3, ab.x, ab.y);
            ab = AB[bb + 3]; frot(v1, v2, ab.x, ab.y);
            ab = AB[bb + 4]; frot(v1, v3, ab.x, ab.y);
            ab = AB[bb + 5]; frot(v2, v3, ab.x, ab.y);

            const float4* abp = (const float4*)(AB + bb + 6);  // 16B-aligned (bb+6 even)
            #pragma unroll 4
            for (int j = i0 + 4; j < DIMN; ++j) {
                float vj = Qs[j * DIMN + t];
                float4 ab01 = abp[0];
                float4 ab23 = abp[1];
                abp += 2;
                frot(v0, vj, ab01.x, ab01.y);
                frot(v1, vj, ab01.z, ab01.w);
                frot(v2, vj, ab23.x, ab23.y);
                frot(v3, vj, ab23.z, ab23.w);
                Qs[j * DIMN + t] = vj;
            }
            Qs[(i0 + 0) * DIMN + t] = v0;
            Qs[(i0 + 1) * DIMN + t] = v1;
            Qs[(i0 + 2) * DIMN + t] = v2;
            Qs[(i0 + 3) * DIMN + t] = v3;
        }
    }

    // ---- output: Q = D * Q~ (no sync needed: thread reads its own column,
    //      rowscale was synced after pass 2) ----
    float* o = out + (size_t)h * DIMN * DIMN;
    for (int idx = tid; idx < DIMN * DIMN; idx += TPB)
        o[idx] = rowscale[idx >> 7] * Qs[idx];
}

extern "C" void kernel_launch(void* const* d_in, const int* in_sizes, int n_in,
                              void* d_out, int out_size)
{
    const float* thetas = (const float*)d_in[0];
    const int*   ri     = (const int*)d_in[1];
    const int*   rj     = (const int*)d_in[2];
    float*       out    = (float*)d_out;

    const size_t smem = SM_FLOATS * sizeof(float);   // 195584 bytes
    cudaFuncSetAttribute(givens_kernel,
                         cudaFuncAttributeMaxDynamicSharedMemorySize, (int)smem);
    givens_kernel<<<NHEADS, TPB, smem>>>(thetas, ri, rj, out);
}

// round 3
// speedup vs baseline: 1.7352x; 1.7352x over previous
#include <cuda_runtime.h>
#include <cuda_bf16.h>

// GivensRotationPerHead: H=64 heads, DIM=128, R=8128 rotations (triu i-major order).
// Round 2 design (resubmit after infra failure):
//   - Split rotation sequence at i=40 (8-row block boundary): Q = B @ A, halves
//     computed independently -> 128 CTAs (87% SM fill) with half the work each.
//   - Fast-Givens (2 FMA/rotation) with per-subsequence prefix scales.
//   - 8-row register blocking; manual software pipeline (prefetch next vj + AB
//     chunk before the store) to break smem load-after-store serialization.
//   - fp32 GEMM kernel combines halves: out = H1 @ H0.

#define NHEADS 64
#define DIMN   128
#define NROT   8128
#define TPB    128

#define SPLIT_I   40         // half0: i in [0,40) (blocks 0..4); half1: i in [40,128)
#define SPLIT_B   5          // first block of half1 (8-row blocks)
#define NB        16         // total 8-row blocks
#define R_SPLIT   4300       // rbase(40)
#define RANGE0    4300
#define RANGE1    3828
#define MAXRANGE  4300

__device__ __forceinline__ int rbase(int i) { return i * 127 - (i * (i - 1)) / 2; }
// base of 8-row block b in blocked AB order (block size = 988 - 64b)
__device__ __forceinline__ int blockbase8(int b) { return 988 * b - 32 * b * (b - 1); }

// fast-givens: vi' = vi + a*vj ; vj' = vj + b*vi_old
__device__ __forceinline__ void frot(float& vi, float& vj, float a, float b) {
    float ni = fmaf(a, vj, vi);
    vj = fmaf(b, vi, vj);
    vi = ni;
}

// 8 MB global scratch: halfQ[task][128][128], task = head*2 + half
__device__ float g_halfQ[2 * NHEADS * DIMN * DIMN];

// ---- smem layout for givens kernel (floats) ----
//  C  [0, 4300)  T [4300, 8600)  Fi [8600,12900)  Fj [12900,17200)
//  Qs aliases [0, 16384) after pass 3
//  AB (float2 x up to 4300) at [17200, 25800)
//  rs [25800, 25928)
#define OFF_T   MAXRANGE
#define OFF_FI  (2 * MAXRANGE)
#define OFF_FJ  (3 * MAXRANGE)
#define OFF_AB  (4 * MAXRANGE)
#define OFF_RS  (4 * MAXRANGE + 2 * MAXRANGE)
#define SM_FLOATS (OFF_RS + DIMN)     // 25928 floats = 103712 B

__global__ __launch_bounds__(TPB)
void givens_half_kernel(const float* __restrict__ thetas,
                        const int*   __restrict__ rot_i,
                        const int*   __restrict__ rot_j)
{
    extern __shared__ float sm[];
    float*  C  = sm;
    float*  T  = sm + OFF_T;
    float*  Fi = sm + OFF_FI;
    float*  Fj = sm + OFF_FJ;
    float*  Qs = sm;                         // aliases C/T/Fi after pass 3
    float2* AB = (float2*)(sm + OFF_AB);
    float*  rs = sm + OFF_RS;

    const int tid  = threadIdx.x;
    const int task = blockIdx.x;
    const int head = task >> 1;
    const int half = task & 1;

    const int r0    = half ? R_SPLIT : 0;
    const int range = half ? RANGE1 : RANGE0;
    const int b_lo  = half ? SPLIT_B : 0;
    const int b_hi  = half ? NB : SPLIT_B;
    const int ilo   = half ? SPLIT_I : 0;
    const int ihi   = half ? DIMN : SPLIT_I;

    const float* th = thetas + (size_t)head * NROT + r0;

    // ---- pass 1: cos / tan over this task's rotation range ----
    for (int rl = tid; rl < range; rl += TPB) {
        float s, c;
        __sincosf(th[rl], &s, &c);
        C[rl] = c;
        T[rl] = __fdividef(s, c);
    }
    __syncthreads();

    // ---- pass 2: per-row prefix products over this subsequence (row = tid) ----
    {
        const int m = tid;
        float f = 1.0f;
        int kend = m < ihi ? m : ihi;
        for (int k = ilo; k < kend; ++k) {          // j-role: rotation (k, m)
            int rl = rbase(k) + (m - k - 1) - r0;
            Fj[rl] = f;
            f *= C[rl];
        }
        if (m >= ilo && m < ihi) {                  // i-role: rotations (m, j)
            int base = rbase(m) - r0;
            for (int j = m + 1; j < DIMN; ++j) {
                int rl = base + (j - m - 1);
                Fi[rl] = f;
                f *= C[rl];
            }
        }
        rs[m] = f;
    }
    __syncthreads();

    // ---- pass 3: alpha/beta into blocked AB table (task-local positions) ----
    for (int rl = tid; rl < range; rl += TPB) {
        int r = r0 + rl;
        int i = rot_i[r];
        int j = rot_j[r];
        float t  = T[rl];
        float fi = Fi[rl];
        float fj = Fj[rl];
        float al =  t * __fdividef(fj, fi);
        float be = -t * __fdividef(fi, fj);
        int b  = i >> 3;
        int a  = i & 7;
        int i0 = b << 3;
        int bb = blockbase8(b) - r0;
        int pos;
        if (j < i0 + 8) {                            // intra-block triangle (28 slots)
            int jj = j - i0;
            pos = bb + a * 7 - (a * (a - 1)) / 2 + (jj - a - 1);
        } else {
            pos = bb + 28 + ((j - i0 - 8) << 3) + a;
        }
        AB[pos] = make_float2(al, be);
    }
    __syncthreads();

    // ---- init Q~ = I (overwrites C/T/Fi region) ----
    for (int idx = tid; idx < DIMN * DIMN; idx += TPB)
        Qs[idx] = ((idx >> 7) == (idx & 127)) ? 1.0f : 0.0f;
    __syncthreads();

    // ---- main loop: blocks of 8 rows in registers, thread t = column t ----
    {
        const int t = tid;
        for (int b = b_lo; b < b_hi; ++b) {
            const int i0 = b << 3;
            const int bb = blockbase8(b) - r0;

            float v[8];
            #pragma unroll
            for (int a = 0; a < 8; ++a) v[a] = Qs[(i0 + a) * DIMN + t];

            // intra-block triangle (28 rotations, original order)
            {
                const float2* abt = AB + bb;
                int p = 0;
                #pragma unroll
                for (int a = 0; a < 7; ++a)
                    #pragma unroll
                    for (int jj = a + 1; jj < 8; ++jj) {
                        float2 ab = abt[p++];
                        frot(v[a], v[jj], ab.x, ab.y);
                    }
            }

            // j-sweep with software pipeline (prefetch next vj + AB before store)
            if (i0 + 8 < DIMN) {
                int j = i0 + 8;
                float vj = Qs[j * DIMN + t];
                const float4* ap = (const float4*)(AB + bb + 28);
                float4 a0 = ap[0], a1 = ap[1], a2 = ap[2], a3 = ap[3];

                #pragma unroll 2
                for (; j < DIMN; ++j) {
                    int jn = (j + 1 < DIMN) ? j + 1 : j;            // clamped prefetch
                    const float4* np =
                        (const float4*)(AB + bb + 28 + ((jn - i0 - 8) << 3));
                    float4 n0 = np[0], n1 = np[1], n2 = np[2], n3 = np[3];
                    float  vn = Qs[jn * DIMN + t];

                    frot(v[0], vj, a0.x, a0.y);
                    frot(v[1], vj, a0.z, a0.w);
                    frot(v[2], vj, a1.x, a1.y);
                    frot(v[3], vj, a1.z, a1.w);
                    frot(v[4], vj, a2.x, a2.y);
                    frot(v[5], vj, a2.z, a2.w);
                    frot(v[6], vj, a3.x, a3.y);
                    frot(v[7], vj, a3.z, a3.w);

                    Qs[j * DIMN + t] = vj;
                    vj = vn;
                    a0 = n0; a1 = n1; a2 = n2; a3 = n3;
                }
            }

            #pragma unroll
            for (int a = 0; a < 8; ++a) Qs[(i0 + a) * DIMN + t] = v[a];
        }
    }
    __syncthreads();

    // ---- write scaled half to global scratch (coalesced) ----
    float* o = g_halfQ + (size_t)task * DIMN * DIMN;
    for (int idx = tid; idx < DIMN * DIMN; idx += TPB)
        o[idx] = rs[idx >> 7] * Qs[idx];
}

// ---- GEMM combine: out[head] = H1 @ H0  (each CTA: 64 rows x 128 cols) ----
#define GTPB 256
#define GSM_FLOATS (DIMN * DIMN + 64 * DIMN)   // sA 16384 + sB 8192

__global__ __launch_bounds__(GTPB)
void combine_kernel(float* __restrict__ out)
{
    extern __shared__ float gs[];
    float* sA = gs;                 // H0 full: [k][c]
    float* sB = gs + DIMN * DIMN;   // H1 rows rh*64..: [r][k]

    const int tid  = threadIdx.x;
    const int head = blockIdx.x >> 1;
    const int rh   = blockIdx.x & 1;

    const float* A = g_halfQ + (size_t)(head * 2 + 0) * DIMN * DIMN;
    const float* B = g_halfQ + (size_t)(head * 2 + 1) * DIMN * DIMN + (size_t)rh * 64 * DIMN;

    for (int idx = tid; idx < DIMN * DIMN / 4; idx += GTPB)
        ((float4*)sA)[idx] = ((const float4*)A)[idx];
    for (int idx = tid; idx < 64 * DIMN / 4; idx += GTPB)
        ((float4*)sB)[idx] = ((const float4*)B)[idx];
    __syncthreads();

    const int tc = tid & 15;        // col tile: 8 cols
    const int tr = tid >> 4;        // row tile: 4 rows
    const int r0 = tr * 4;
    const int c0 = tc * 8;

    float acc[4][8];
    #pragma unroll
    for (int i = 0; i < 4; ++i)
        #pragma unroll
        for (int jj = 0; jj < 8; ++jj) acc[i][jj] = 0.0f;

    for (int k = 0; k < DIMN; k += 4) {
        float4 av[4];
        #pragma unroll
        for (int i = 0; i < 4; ++i)
            av[i] = *(const float4*)&sB[(r0 + i) * DIMN + k];
        #pragma unroll
        for (int kk = 0; kk < 4; ++kk) {
            float4 b0 = *(const float4*)&sA[(k + kk) * DIMN + c0];
            float4 b1 = *(const float4*)&sA[(k + kk) * DIMN + c0 + 4];
            #pragma unroll
            for (int i = 0; i < 4; ++i) {
                float a = (kk == 0) ? av[i].x : (kk == 1) ? av[i].y
                        : (kk == 2) ? av[i].z : av[i].w;
                acc[i][0] = fmaf(a, b0.x, acc[i][0]);
                acc[i][1] = fmaf(a, b0.y, acc[i][1]);
                acc[i][2] = fmaf(a, b0.z, acc[i][2]);
                acc[i][3] = fmaf(a, b0.w, acc[i][3]);
                acc[i][4] = fmaf(a, b1.x, acc[i][4]);
                acc[i][5] = fmaf(a, b1.y, acc[i][5]);
                acc[i][6] = fmaf(a, b1.z, acc[i][6]);
                acc[i][7] = fmaf(a, b1.w, acc[i][7]);
            }
        }
    }

    float* o = out + (size_t)head * DIMN * DIMN + (size_t)(rh * 64 + r0) * DIMN + c0;
    #pragma unroll
    for (int i = 0; i < 4; ++i) {
        *(float4*)(o + i * DIMN)     = make_float4(acc[i][0], acc[i][1], acc[i][2], acc[i][3]);
        *(float4*)(o + i * DIMN + 4) = make_float4(acc[i][4], acc[i][5], acc[i][6], acc[i][7]);
    }
}

extern "C" void kernel_launch(void* const* d_in, const int* in_sizes, int n_in,
                              void* d_out, int out_size)
{
    const float* thetas = (const float*)d_in[0];
    const int*   ri     = (const int*)d_in[1];
    const int*   rj     = (const int*)d_in[2];
    float*       out    = (float*)d_out;

    const size_t smem1 = SM_FLOATS * sizeof(float);    // 103712 B
    const size_t smem2 = GSM_FLOATS * sizeof(float);   //  98304 B
    cudaFuncSetAttribute(givens_half_kernel,
                         cudaFuncAttributeMaxDynamicSharedMemorySize, (int)smem1);
    cudaFuncSetAttribute(combine_kernel,
                         cudaFuncAttributeMaxDynamicSharedMemorySize, (int)smem2);

    givens_half_kernel<<<2 * NHEADS, TPB, smem1>>>(thetas, ri, rj);
    combine_kernel<<<2 * NHEADS, GTPB, smem2>>>(out);
}